// round 12
// baseline (speedup 1.0000x reference)
#include <cuda_runtime.h>
#include <cuda_fp16.h>
#include <cstdint>

#define NN 50000
#define EE 800000
#define RR 4
#define CC 4
#define GG 512
#define NBLK 196          // (NN + 255) / 256

// ---------------- device scratch (static, no allocation) ----------------
__device__ float g_Wt1[320 * 64];                   // Wt[c][k], tf32-rounded bits
__device__ float g_Wt2[320 * 64];
__device__ __half2 g_h2[(size_t)RR * NN * 32];      // per-relation messages, fp16
__device__ float g_agg1[(size_t)NN * 64];           // self+bias then += scaled messages
__device__ float g_agg2[(size_t)NN * 64];           // layer2 self
__device__ float g_cnt[RR * NN];
__device__ float g_inv[RR * NN];
__device__ int   g_deg[NN];
__device__ int   g_bsum[NBLK];
__device__ int   g_off[NN + 1];
__device__ int   g_fill[NN];
__device__ __align__(16) unsigned g_eperm[EE];      // (et<<16)|src grouped by dst
__device__ float g_pool[GG * 64];

__device__ __forceinline__ uint32_t f2tf32(float x) {
    uint32_t u;
    asm("cvt.rna.tf32.f32 %0, %1;" : "=r"(u) : "f"(x));
    return u;
}

// ---------------- fused init: zero accumulators + weight prep ----------------
__global__ void init_fused(const float* __restrict__ b1, const float* __restrict__ c1,
                           const float* __restrict__ r1, const float* __restrict__ b2,
                           const float* __restrict__ c2, const float* __restrict__ r2) {
    int t = blockIdx.x * blockDim.x + threadIdx.x;
    int stride = gridDim.x * blockDim.x;
    for (int i = t; i < RR * NN; i += stride) g_cnt[i] = 0.f;
    for (int i = t; i < NN; i += stride) g_fill[i] = 0;
    for (int i = t; i < GG * 64; i += stride) g_pool[i] = 0.f;

    for (int w = t; w < 2 * 320 * 64; w += stride) {
        int layer = w / 20480;
        int i = w % 20480;
        int c = i / 64;
        int k = i % 64;
        const float* basis = layer ? b2 : b1;
        const float* comp  = layer ? c2 : c1;
        const float* root  = layer ? r2 : r1;
        float v;
        if (c < 256) {
            int r = c >> 6, o = c & 63;
            v = 0.f;
#pragma unroll
            for (int b = 0; b < 4; b++)
                v += comp[r * 4 + b] * basis[((size_t)b * 64 + k) * 64 + o];
        } else {
            v = root[k * 64 + (c - 256)];
        }
        (layer ? g_Wt2 : g_Wt1)[c * 64 + k] = __uint_as_float(f2tf32(v));
    }
}

// ---------------- per-(relation,dst) edge counts ----------------
__global__ void count_edges(const int* __restrict__ dst, const int* __restrict__ et) {
    int e = blockIdx.x * blockDim.x + threadIdx.x;
    if (e >= EE) return;
    atomicAdd(&g_cnt[et[e] * NN + dst[e]], 1.0f);
}

// ---------------- scan phase 1: deg + inv from cnt, per-block sums ----------------
__global__ void __launch_bounds__(256) scan_phase1() {
    __shared__ int sh[256];
    int t = threadIdx.x;
    int i = blockIdx.x * 256 + t;
    int d = 0;
    if (i < NN) {
        float c0 = g_cnt[i], c1 = g_cnt[NN + i], c2 = g_cnt[2 * NN + i], c3 = g_cnt[3 * NN + i];
        g_inv[i]          = 1.0f / fmaxf(c0, 1.f);
        g_inv[NN + i]     = 1.0f / fmaxf(c1, 1.f);
        g_inv[2 * NN + i] = 1.0f / fmaxf(c2, 1.f);
        g_inv[3 * NN + i] = 1.0f / fmaxf(c3, 1.f);
        d = (int)(c0 + c1 + c2 + c3);
        g_deg[i] = d;
    }
    sh[t] = d;
    __syncthreads();
#pragma unroll
    for (int s = 128; s > 0; s >>= 1) {
        if (t < s) sh[t] += sh[t + s];
        __syncthreads();
    }
    if (t == 0) g_bsum[blockIdx.x] = sh[0];
}

// ---------------- scan phase 2: block offset + intra-block scan ----------------
__global__ void __launch_bounds__(256) scan_phase2() {
    __shared__ int sh[256];
    int bid = blockIdx.x, t = threadIdx.x;

    sh[t] = (t < bid) ? g_bsum[t] : 0;      // bid < NBLK <= 256
    __syncthreads();
#pragma unroll
    for (int s = 128; s > 0; s >>= 1) {
        if (t < s) sh[t] += sh[t + s];
        __syncthreads();
    }
    int blockOff = sh[0];
    __syncthreads();

    int i = bid * 256 + t;
    int v = (i < NN) ? g_deg[i] : 0;
    sh[t] = v;
    __syncthreads();
#pragma unroll
    for (int s = 1; s < 256; s <<= 1) {
        int x = (t >= s) ? sh[t - s] : 0;
        __syncthreads();
        sh[t] += x;
        __syncthreads();
    }
    int excl = sh[t] - v;
    if (i <= NN) g_off[i] = blockOff + excl;
}

__global__ void build_perm(const int* __restrict__ src, const int* __restrict__ dst,
                           const int* __restrict__ et) {
    int e = blockIdx.x * blockDim.x + threadIdx.x;
    if (e >= EE) return;
    int d = dst[e];
    int pos = g_off[d] + atomicAdd(&g_fill[d], 1);
    g_eperm[pos] = ((unsigned)et[e] << 16) | (unsigned)src[e];
}

// ================= tf32 mma.sync GEMM: [128,64] @ [64,320] per CTA =================
#define SPAD 68
#define AS_FLOATS (128 * SPAD)
#define BS_FLOATS (320 * SPAD)
#define GEMM_SMEM ((AS_FLOATS + BS_FLOATS) * 4)

__global__ void __launch_bounds__(256)
gemm_tc(const float* __restrict__ Xin, const float* __restrict__ bias, int layer) {
    extern __shared__ float smem[];
    float* As = smem;                  // [128][68]
    float* Bs = smem + AS_FLOATS;      // [320][68]
    __shared__ float s_bias[64];

    const float* X = layer ? g_agg1 : Xin;
    const float* W = layer ? g_Wt2 : g_Wt1;
    float* aggOut = layer ? g_agg2 : g_agg1;
    const bool doRelu = (layer == 1);

    int t = threadIdx.x;
    int wid = t >> 5, lane = t & 31;
    int nodeBase = blockIdx.x * 128;
    if (t < 64) s_bias[t] = bias[t];

#pragma unroll
    for (int i = 0; i < 8; i++) {
        int f = t + i * 256;
        int row = f >> 4;
        int k4 = (f & 15) << 2;
        int gn = nodeBase + row;
        float4 v = make_float4(0.f, 0.f, 0.f, 0.f);
        if (gn < NN) v = *(const float4*)(X + (size_t)gn * 64 + k4);
        if (doRelu) {
            v.x = fmaxf(v.x, 0.f); v.y = fmaxf(v.y, 0.f);
            v.z = fmaxf(v.z, 0.f); v.w = fmaxf(v.w, 0.f);
        }
        float* d = As + row * SPAD + k4;
        d[0] = __uint_as_float(f2tf32(v.x));
        d[1] = __uint_as_float(f2tf32(v.y));
        d[2] = __uint_as_float(f2tf32(v.z));
        d[3] = __uint_as_float(f2tf32(v.w));
    }
#pragma unroll
    for (int i = 0; i < 20; i++) {
        int f = t + i * 256;
        int row = f >> 4;
        int k4 = (f & 15) << 2;
        *(float4*)(Bs + row * SPAD + k4) = *(const float4*)(W + (size_t)row * 64 + k4);
    }
    __syncthreads();

    int qrow = lane >> 2;
    int qcol = lane & 3;
    const float* Abase = As + (wid * 16 + qrow) * SPAD + qcol;
    const float* Bbase = Bs + qrow * SPAD + qcol;

#pragma unroll
    for (int j = 0; j < 5; j++) {
        float c[8][4];
#pragma unroll
        for (int nt = 0; nt < 8; nt++)
#pragma unroll
            for (int q = 0; q < 4; q++) c[nt][q] = 0.f;

#pragma unroll
        for (int ks = 0; ks < 8; ks++) {
            int k = ks * 8;
            uint32_t a0 = __float_as_uint(Abase[k]);
            uint32_t a1 = __float_as_uint(Abase[8 * SPAD + k]);
            uint32_t a2 = __float_as_uint(Abase[k + 4]);
            uint32_t a3 = __float_as_uint(Abase[8 * SPAD + k + 4]);
#pragma unroll
            for (int nt = 0; nt < 8; nt++) {
                const float* bp = Bbase + (j * 64 + nt * 8) * SPAD + k;
                uint32_t b0 = __float_as_uint(bp[0]);
                uint32_t b1 = __float_as_uint(bp[4]);
                asm volatile(
                    "mma.sync.aligned.m16n8k8.row.col.f32.tf32.tf32.f32 "
                    "{%0,%1,%2,%3}, {%4,%5,%6,%7}, {%8,%9}, {%0,%1,%2,%3};"
                    : "+f"(c[nt][0]), "+f"(c[nt][1]), "+f"(c[nt][2]), "+f"(c[nt][3])
                    : "r"(a0), "r"(a1), "r"(a2), "r"(a3), "r"(b0), "r"(b1));
            }
        }

        int node0 = nodeBase + wid * 16 + qrow;
        int node1 = node0 + 8;
        if (j < 4) {
            __half2* h0 = g_h2 + ((size_t)j * NN + node0) * 32 + qcol;
            __half2* h1 = g_h2 + ((size_t)j * NN + node1) * 32 + qcol;
#pragma unroll
            for (int nt = 0; nt < 8; nt++) {
                if (node0 < NN) h0[nt * 4] = __floats2half2_rn(c[nt][0], c[nt][1]);
                if (node1 < NN) h1[nt * 4] = __floats2half2_rn(c[nt][2], c[nt][3]);
            }
        } else {
            float* a0p = aggOut + (size_t)node0 * 64 + qcol * 2;
            float* a1p = aggOut + (size_t)node1 * 64 + qcol * 2;
#pragma unroll
            for (int nt = 0; nt < 8; nt++) {
                float bx = s_bias[nt * 8 + qcol * 2];
                float by = s_bias[nt * 8 + qcol * 2 + 1];
                if (node0 < NN) *(float2*)(a0p + nt * 8) = make_float2(c[nt][0] + bx, c[nt][1] + by);
                if (node1 < NN) *(float2*)(a1p + nt * 8) = make_float2(c[nt][2] + bx, c[nt][3] + by);
            }
        }
    }
}

// ---------------- segmented aggregation: one warp per dst ----------------
// Issue-diet mainloop: 1 uint4 eperm load + 4 gathers per 4 edges; inv selected
// from 4 hoisted registers (ALU SELs, off the LSU). Accumulation fp32.
__device__ __forceinline__ float sel_inv(unsigned r, float i0, float i1, float i2, float i3) {
    float a = (r == 0) ? i0 : i1;
    float b = (r == 2) ? i2 : i3;
    return (r < 2) ? a : b;
}

__global__ void __launch_bounds__(256) agg_edges(const int* __restrict__ batch, int layer) {
    int w = (blockIdx.x * blockDim.x + threadIdx.x) >> 5;
    if (w >= NN) return;
    int lane = threadIdx.x & 31;
    int beg = g_off[w], end = g_off[w + 1];

    float inv0 = g_inv[w];
    float inv1 = g_inv[NN + w];
    float inv2 = g_inv[2 * NN + w];
    float inv3 = g_inv[3 * NN + w];

    float* agg = (layer ? g_agg2 : g_agg1) + (size_t)w * 64 + lane * 2;
    float2 a0 = *(float2*)agg;                         // self + bias from GEMM
    float2 a1 = make_float2(0.f, 0.f);
    float2 a2 = make_float2(0.f, 0.f);
    float2 a3 = make_float2(0.f, 0.f);

    const __half2* hb = g_h2 + lane;

    int e = beg;
    // peel to 16B alignment of &g_eperm[e]
    for (; e < end && (e & 3); e++) {
        unsigned p = g_eperm[e];
        float iv = sel_inv(p >> 16, inv0, inv1, inv2, inv3);
        float2 v = __half22float2(hb[(((size_t)(p >> 16)) * NN + (p & 0xFFFF)) * 32]);
        a0.x += v.x * iv; a0.y += v.y * iv;
    }
    for (; e + 3 < end; e += 4) {
        uint4 pk = *(const uint4*)&g_eperm[e];         // one LDG.128, uniform
        float2 v0 = __half22float2(hb[(((size_t)(pk.x >> 16)) * NN + (pk.x & 0xFFFF)) * 32]);
        float2 v1 = __half22float2(hb[(((size_t)(pk.y >> 16)) * NN + (pk.y & 0xFFFF)) * 32]);
        float2 v2 = __half22float2(hb[(((size_t)(pk.z >> 16)) * NN + (pk.z & 0xFFFF)) * 32]);
        float2 v3 = __half22float2(hb[(((size_t)(pk.w >> 16)) * NN + (pk.w & 0xFFFF)) * 32]);
        float i0 = sel_inv(pk.x >> 16, inv0, inv1, inv2, inv3);
        float i1 = sel_inv(pk.y >> 16, inv0, inv1, inv2, inv3);
        float i2 = sel_inv(pk.z >> 16, inv0, inv1, inv2, inv3);
        float i3 = sel_inv(pk.w >> 16, inv0, inv1, inv2, inv3);
        a0.x += v0.x * i0; a0.y += v0.y * i0;
        a1.x += v1.x * i1; a1.y += v1.y * i1;
        a2.x += v2.x * i2; a2.y += v2.y * i2;
        a3.x += v3.x * i3; a3.y += v3.y * i3;
    }
    for (; e < end; e++) {
        unsigned p = g_eperm[e];
        float iv = sel_inv(p >> 16, inv0, inv1, inv2, inv3);
        float2 v = __half22float2(hb[(((size_t)(p >> 16)) * NN + (p & 0xFFFF)) * 32]);
        a0.x += v.x * iv; a0.y += v.y * iv;
    }
    a0.x += a1.x + a2.x + a3.x;
    a0.y += a1.y + a2.y + a3.y;

    if (layer == 0) {
        *(float2*)agg = a0;                            // relu applied by layer-2 gemm load
    } else {
        float rx = fmaxf(a0.x, 0.f);
        float ry = fmaxf(a0.y, 0.f);
        float* p = g_pool + batch[w] * 64 + lane * 2;
        asm volatile("red.global.add.v2.f32 [%0], {%1,%2};"
                     :: "l"(p), "f"(rx), "f"(ry) : "memory");
    }
}

// ---------------- classifier: counts via binary search on sorted batch ---------
__global__ void classify(const int* __restrict__ batch, const float* __restrict__ w,
                         const float* __restrict__ b, float* __restrict__ out) {
    int t = blockIdx.x * blockDim.x + threadIdx.x;
    if (t >= GG * CC) return;
    int g = t / CC, c = t % CC;
    int lo = 0, hi = NN;
    while (lo < hi) { int m = (lo + hi) >> 1; if (batch[m] < g) lo = m + 1; else hi = m; }
    int lo2 = lo, hi2 = NN;
    while (lo2 < hi2) { int m = (lo2 + hi2) >> 1; if (batch[m] < g + 1) lo2 = m + 1; else hi2 = m; }
    float inv = 1.f / fmaxf((float)(lo2 - lo), 1.f);
    float acc = b[c];
#pragma unroll
    for (int k = 0; k < 64; k++)
        acc += g_pool[g * 64 + k] * inv * w[k * CC + c];
    out[t] = acc;
}

// ---------------- launch ----------------
extern "C" void kernel_launch(void* const* d_in, const int* in_sizes, int n_in,
                              void* d_out, int out_size) {
    const float* x      = (const float*)d_in[0];
    const int*   ei     = (const int*)d_in[1];
    const int*   et     = (const int*)d_in[2];
    const int*   batch  = (const int*)d_in[3];
    const float* basis1 = (const float*)d_in[4];
    const float* comp1  = (const float*)d_in[5];
    const float* root1  = (const float*)d_in[6];
    const float* bias1  = (const float*)d_in[7];
    const float* basis2 = (const float*)d_in[8];
    const float* comp2  = (const float*)d_in[9];
    const float* root2  = (const float*)d_in[10];
    const float* bias2  = (const float*)d_in[11];
    const float* clw    = (const float*)d_in[12];
    const float* clb    = (const float*)d_in[13];
    float* out = (float*)d_out;

    const int* src = ei;
    const int* dstp = ei + EE;

    static int inited = 0;
    if (!inited) {
        cudaFuncSetAttribute(gemm_tc, cudaFuncAttributeMaxDynamicSharedMemorySize,
                             GEMM_SMEM);
        inited = 1;
    }

    int gblocks = (NN + 127) / 128;   // 391

    // ---- preprocessing ----
    init_fused<<<320, 256>>>(basis1, comp1, root1, basis2, comp2, root2);
    count_edges<<<EE / 256, 256>>>(dstp, et);
    scan_phase1<<<NBLK, 256>>>();
    scan_phase2<<<NBLK, 256>>>();
    build_perm<<<EE / 256, 256>>>(src, dstp, et);

    // ---- layer 1 ----
    gemm_tc<<<gblocks, 256, GEMM_SMEM>>>(x, bias1, 0);
    agg_edges<<<(NN * 32 + 255) / 256, 256>>>(batch, 0);

    // ---- layer 2 ----
    gemm_tc<<<gblocks, 256, GEMM_SMEM>>>(x, bias2, 1);
    agg_edges<<<(NN * 32 + 255) / 256, 256>>>(batch, 1);   // fused relu + pool

    // ---- classifier ----
    classify<<<(GG * CC + 255) / 256, 256>>>(batch, clw, clb, out);
}

// round 13
// speedup vs baseline: 1.0137x; 1.0137x over previous
#include <cuda_runtime.h>
#include <cuda_fp16.h>
#include <cstdint>

#define NN 50000
#define EE 800000
#define RR 4
#define CC 4
#define GG 512
#define NBLK 196          // (NN + 255) / 256

// ---------------- device scratch (static, no allocation) ----------------
__device__ float g_Wt1[320 * 64];                   // Wt[c][k], tf32-rounded bits
__device__ float g_Wt2[320 * 64];
__device__ __half2 g_h2[(size_t)RR * NN * 32];      // per-relation messages, fp16
__device__ float g_agg1[(size_t)NN * 64];           // self+bias then += scaled messages
__device__ float g_agg2[(size_t)NN * 64];           // layer2 self
__device__ float g_cnt[RR * NN];
__device__ float g_inv[RR * NN];
__device__ int   g_deg[NN];
__device__ int   g_bsum[NBLK];
__device__ int   g_off[NN + 1];
__device__ int   g_fill[NN];
__device__ unsigned g_eperm[EE];                    // (et<<16)|src grouped by dst
__device__ float g_pool[GG * 64];

__device__ __forceinline__ uint32_t f2tf32(float x) {
    uint32_t u;
    asm("cvt.rna.tf32.f32 %0, %1;" : "=r"(u) : "f"(x));
    return u;
}

// ---------------- fused init: zero accumulators + weight prep ----------------
__global__ void init_fused(const float* __restrict__ b1, const float* __restrict__ c1,
                           const float* __restrict__ r1, const float* __restrict__ b2,
                           const float* __restrict__ c2, const float* __restrict__ r2) {
    int t = blockIdx.x * blockDim.x + threadIdx.x;
    int stride = gridDim.x * blockDim.x;
    for (int i = t; i < RR * NN; i += stride) g_cnt[i] = 0.f;
    for (int i = t; i < NN; i += stride) g_fill[i] = 0;
    for (int i = t; i < GG * 64; i += stride) g_pool[i] = 0.f;

    for (int w = t; w < 2 * 320 * 64; w += stride) {
        int layer = w / 20480;
        int i = w % 20480;
        int c = i / 64;
        int k = i % 64;
        const float* basis = layer ? b2 : b1;
        const float* comp  = layer ? c2 : c1;
        const float* root  = layer ? r2 : r1;
        float v;
        if (c < 256) {
            int r = c >> 6, o = c & 63;
            v = 0.f;
#pragma unroll
            for (int b = 0; b < 4; b++)
                v += comp[r * 4 + b] * basis[((size_t)b * 64 + k) * 64 + o];
        } else {
            v = root[k * 64 + (c - 256)];
        }
        (layer ? g_Wt2 : g_Wt1)[c * 64 + k] = __uint_as_float(f2tf32(v));
    }
}

// ---------------- per-(relation,dst) edge counts ----------------
__global__ void count_edges(const int* __restrict__ dst, const int* __restrict__ et) {
    int e = blockIdx.x * blockDim.x + threadIdx.x;
    if (e >= EE) return;
    atomicAdd(&g_cnt[et[e] * NN + dst[e]], 1.0f);
}

// ---------------- scan phase 1: deg + inv from cnt, per-block sums ----------------
__global__ void __launch_bounds__(256) scan_phase1() {
    __shared__ int sh[256];
    int t = threadIdx.x;
    int i = blockIdx.x * 256 + t;
    int d = 0;
    if (i < NN) {
        float c0 = g_cnt[i], c1 = g_cnt[NN + i], c2 = g_cnt[2 * NN + i], c3 = g_cnt[3 * NN + i];
        g_inv[i]          = 1.0f / fmaxf(c0, 1.f);
        g_inv[NN + i]     = 1.0f / fmaxf(c1, 1.f);
        g_inv[2 * NN + i] = 1.0f / fmaxf(c2, 1.f);
        g_inv[3 * NN + i] = 1.0f / fmaxf(c3, 1.f);
        d = (int)(c0 + c1 + c2 + c3);
        g_deg[i] = d;
    }
    sh[t] = d;
    __syncthreads();
#pragma unroll
    for (int s = 128; s > 0; s >>= 1) {
        if (t < s) sh[t] += sh[t + s];
        __syncthreads();
    }
    if (t == 0) g_bsum[blockIdx.x] = sh[0];
}

// ---------------- scan phase 2: block offset + intra-block scan ----------------
__global__ void __launch_bounds__(256) scan_phase2() {
    __shared__ int sh[256];
    int bid = blockIdx.x, t = threadIdx.x;

    sh[t] = (t < bid) ? g_bsum[t] : 0;      // bid < NBLK <= 256
    __syncthreads();
#pragma unroll
    for (int s = 128; s > 0; s >>= 1) {
        if (t < s) sh[t] += sh[t + s];
        __syncthreads();
    }
    int blockOff = sh[0];
    __syncthreads();

    int i = bid * 256 + t;
    int v = (i < NN) ? g_deg[i] : 0;
    sh[t] = v;
    __syncthreads();
#pragma unroll
    for (int s = 1; s < 256; s <<= 1) {
        int x = (t >= s) ? sh[t - s] : 0;
        __syncthreads();
        sh[t] += x;
        __syncthreads();
    }
    int excl = sh[t] - v;
    if (i <= NN) g_off[i] = blockOff + excl;
}

__global__ void build_perm(const int* __restrict__ src, const int* __restrict__ dst,
                           const int* __restrict__ et) {
    int e = blockIdx.x * blockDim.x + threadIdx.x;
    if (e >= EE) return;
    int d = dst[e];
    int pos = g_off[d] + atomicAdd(&g_fill[d], 1);
    g_eperm[pos] = ((unsigned)et[e] << 16) | (unsigned)src[e];
}

// ================= tf32 mma.sync GEMM: [128,64] @ [64,320] per CTA =================
#define SPAD 68
#define AS_FLOATS (128 * SPAD)
#define BS_FLOATS (320 * SPAD)
#define GEMM_SMEM ((AS_FLOATS + BS_FLOATS) * 4)

__global__ void __launch_bounds__(256)
gemm_tc(const float* __restrict__ Xin, const float* __restrict__ bias, int layer) {
    extern __shared__ float smem[];
    float* As = smem;                  // [128][68]
    float* Bs = smem + AS_FLOATS;      // [320][68]
    __shared__ float s_bias[64];

    const float* X = layer ? g_agg1 : Xin;
    const float* W = layer ? g_Wt2 : g_Wt1;
    float* aggOut = layer ? g_agg2 : g_agg1;
    const bool doRelu = (layer == 1);

    int t = threadIdx.x;
    int wid = t >> 5, lane = t & 31;
    int nodeBase = blockIdx.x * 128;
    if (t < 64) s_bias[t] = bias[t];

#pragma unroll
    for (int i = 0; i < 8; i++) {
        int f = t + i * 256;
        int row = f >> 4;
        int k4 = (f & 15) << 2;
        int gn = nodeBase + row;
        float4 v = make_float4(0.f, 0.f, 0.f, 0.f);
        if (gn < NN) v = *(const float4*)(X + (size_t)gn * 64 + k4);
        if (doRelu) {
            v.x = fmaxf(v.x, 0.f); v.y = fmaxf(v.y, 0.f);
            v.z = fmaxf(v.z, 0.f); v.w = fmaxf(v.w, 0.f);
        }
        float* d = As + row * SPAD + k4;
        d[0] = __uint_as_float(f2tf32(v.x));
        d[1] = __uint_as_float(f2tf32(v.y));
        d[2] = __uint_as_float(f2tf32(v.z));
        d[3] = __uint_as_float(f2tf32(v.w));
    }
#pragma unroll
    for (int i = 0; i < 20; i++) {
        int f = t + i * 256;
        int row = f >> 4;
        int k4 = (f & 15) << 2;
        *(float4*)(Bs + row * SPAD + k4) = *(const float4*)(W + (size_t)row * 64 + k4);
    }
    __syncthreads();

    int qrow = lane >> 2;
    int qcol = lane & 3;
    const float* Abase = As + (wid * 16 + qrow) * SPAD + qcol;
    const float* Bbase = Bs + qrow * SPAD + qcol;

#pragma unroll
    for (int j = 0; j < 5; j++) {
        float c[8][4];
#pragma unroll
        for (int nt = 0; nt < 8; nt++)
#pragma unroll
            for (int q = 0; q < 4; q++) c[nt][q] = 0.f;

#pragma unroll
        for (int ks = 0; ks < 8; ks++) {
            int k = ks * 8;
            uint32_t a0 = __float_as_uint(Abase[k]);
            uint32_t a1 = __float_as_uint(Abase[8 * SPAD + k]);
            uint32_t a2 = __float_as_uint(Abase[k + 4]);
            uint32_t a3 = __float_as_uint(Abase[8 * SPAD + k + 4]);
#pragma unroll
            for (int nt = 0; nt < 8; nt++) {
                const float* bp = Bbase + (j * 64 + nt * 8) * SPAD + k;
                uint32_t b0 = __float_as_uint(bp[0]);
                uint32_t b1 = __float_as_uint(bp[4]);
                asm volatile(
                    "mma.sync.aligned.m16n8k8.row.col.f32.tf32.tf32.f32 "
                    "{%0,%1,%2,%3}, {%4,%5,%6,%7}, {%8,%9}, {%0,%1,%2,%3};"
                    : "+f"(c[nt][0]), "+f"(c[nt][1]), "+f"(c[nt][2]), "+f"(c[nt][3])
                    : "r"(a0), "r"(a1), "r"(a2), "r"(a3), "r"(b0), "r"(b1));
            }
        }

        int node0 = nodeBase + wid * 16 + qrow;
        int node1 = node0 + 8;
        if (j < 4) {
            __half2* h0 = g_h2 + ((size_t)j * NN + node0) * 32 + qcol;
            __half2* h1 = g_h2 + ((size_t)j * NN + node1) * 32 + qcol;
#pragma unroll
            for (int nt = 0; nt < 8; nt++) {
                if (node0 < NN) h0[nt * 4] = __floats2half2_rn(c[nt][0], c[nt][1]);
                if (node1 < NN) h1[nt * 4] = __floats2half2_rn(c[nt][2], c[nt][3]);
            }
        } else {
            float* a0p = aggOut + (size_t)node0 * 64 + qcol * 2;
            float* a1p = aggOut + (size_t)node1 * 64 + qcol * 2;
#pragma unroll
            for (int nt = 0; nt < 8; nt++) {
                float bx = s_bias[nt * 8 + qcol * 2];
                float by = s_bias[nt * 8 + qcol * 2 + 1];
                if (node0 < NN) *(float2*)(a0p + nt * 8) = make_float2(c[nt][0] + bx, c[nt][1] + by);
                if (node1 < NN) *(float2*)(a1p + nt * 8) = make_float2(c[nt][2] + bx, c[nt][3] + by);
            }
        }
    }
}

// ---------------- segmented aggregation: one warp per dst, 4-way unroll --------
// R11 structure (independent scalar eperm loads, fp16 gathers) + hoisted inv SELs.
__device__ __forceinline__ float sel_inv(unsigned r, float i0, float i1, float i2, float i3) {
    float a = (r == 0) ? i0 : i1;
    float b = (r == 2) ? i2 : i3;
    return (r < 2) ? a : b;
}

__global__ void __launch_bounds__(256) agg_edges(const int* __restrict__ batch, int layer) {
    int w = (blockIdx.x * blockDim.x + threadIdx.x) >> 5;
    if (w >= NN) return;
    int lane = threadIdx.x & 31;
    int beg = g_off[w], end = g_off[w + 1];

    float inv0 = g_inv[w];
    float inv1 = g_inv[NN + w];
    float inv2 = g_inv[2 * NN + w];
    float inv3 = g_inv[3 * NN + w];

    float* agg = (layer ? g_agg2 : g_agg1) + (size_t)w * 64 + lane * 2;
    float2 a0 = *(float2*)agg;                         // self + bias from GEMM
    float2 a1 = make_float2(0.f, 0.f);
    float2 a2 = make_float2(0.f, 0.f);
    float2 a3 = make_float2(0.f, 0.f);

    const __half2* hb = g_h2 + lane;

    int e = beg;
    for (; e + 3 < end; e += 4) {
        unsigned p0 = g_eperm[e], p1 = g_eperm[e + 1];
        unsigned p2 = g_eperm[e + 2], p3 = g_eperm[e + 3];
        float2 v0 = __half22float2(hb[(((size_t)(p0 >> 16)) * NN + (p0 & 0xFFFF)) * 32]);
        float2 v1 = __half22float2(hb[(((size_t)(p1 >> 16)) * NN + (p1 & 0xFFFF)) * 32]);
        float2 v2 = __half22float2(hb[(((size_t)(p2 >> 16)) * NN + (p2 & 0xFFFF)) * 32]);
        float2 v3 = __half22float2(hb[(((size_t)(p3 >> 16)) * NN + (p3 & 0xFFFF)) * 32]);
        float i0 = sel_inv(p0 >> 16, inv0, inv1, inv2, inv3);
        float i1 = sel_inv(p1 >> 16, inv0, inv1, inv2, inv3);
        float i2 = sel_inv(p2 >> 16, inv0, inv1, inv2, inv3);
        float i3 = sel_inv(p3 >> 16, inv0, inv1, inv2, inv3);
        a0.x += v0.x * i0; a0.y += v0.y * i0;
        a1.x += v1.x * i1; a1.y += v1.y * i1;
        a2.x += v2.x * i2; a2.y += v2.y * i2;
        a3.x += v3.x * i3; a3.y += v3.y * i3;
    }
    for (; e < end; e++) {
        unsigned p = g_eperm[e];
        float iv = sel_inv(p >> 16, inv0, inv1, inv2, inv3);
        float2 v = __half22float2(hb[(((size_t)(p >> 16)) * NN + (p & 0xFFFF)) * 32]);
        a0.x += v.x * iv; a0.y += v.y * iv;
    }
    a0.x += a1.x + a2.x + a3.x;
    a0.y += a1.y + a2.y + a3.y;

    if (layer == 0) {
        *(float2*)agg = a0;                            // relu applied by layer-2 gemm load
    } else {
        float rx = fmaxf(a0.x, 0.f);
        float ry = fmaxf(a0.y, 0.f);
        float* p = g_pool + batch[w] * 64 + lane * 2;
        asm volatile("red.global.add.v2.f32 [%0], {%1,%2};"
                     :: "l"(p), "f"(rx), "f"(ry) : "memory");
    }
}

// ---------------- classifier: counts via binary search on sorted batch ---------
__global__ void classify(const int* __restrict__ batch, const float* __restrict__ w,
                         const float* __restrict__ b, float* __restrict__ out) {
    int t = blockIdx.x * blockDim.x + threadIdx.x;
    if (t >= GG * CC) return;
    int g = t / CC, c = t % CC;
    int lo = 0, hi = NN;
    while (lo < hi) { int m = (lo + hi) >> 1; if (batch[m] < g) lo = m + 1; else hi = m; }
    int lo2 = lo, hi2 = NN;
    while (lo2 < hi2) { int m = (lo2 + hi2) >> 1; if (batch[m] < g + 1) lo2 = m + 1; else hi2 = m; }
    float inv = 1.f / fmaxf((float)(lo2 - lo), 1.f);
    float acc = b[c];
#pragma unroll
    for (int k = 0; k < 64; k++)
        acc += g_pool[g * 64 + k] * inv * w[k * CC + c];
    out[t] = acc;
}

// ---------------- launch ----------------
extern "C" void kernel_launch(void* const* d_in, const int* in_sizes, int n_in,
                              void* d_out, int out_size) {
    const float* x      = (const float*)d_in[0];
    const int*   ei     = (const int*)d_in[1];
    const int*   et     = (const int*)d_in[2];
    const int*   batch  = (const int*)d_in[3];
    const float* basis1 = (const float*)d_in[4];
    const float* comp1  = (const float*)d_in[5];
    const float* root1  = (const float*)d_in[6];
    const float* bias1  = (const float*)d_in[7];
    const float* basis2 = (const float*)d_in[8];
    const float* comp2  = (const float*)d_in[9];
    const float* root2  = (const float*)d_in[10];
    const float* bias2  = (const float*)d_in[11];
    const float* clw    = (const float*)d_in[12];
    const float* clb    = (const float*)d_in[13];
    float* out = (float*)d_out;

    const int* src = ei;
    const int* dstp = ei + EE;

    static int inited = 0;
    if (!inited) {
        cudaFuncSetAttribute(gemm_tc, cudaFuncAttributeMaxDynamicSharedMemorySize,
                             GEMM_SMEM);
        inited = 1;
    }

    int gblocks = (NN + 127) / 128;   // 391

    // ---- preprocessing ----
    init_fused<<<320, 256>>>(basis1, comp1, root1, basis2, comp2, root2);
    count_edges<<<EE / 256, 256>>>(dstp, et);
    scan_phase1<<<NBLK, 256>>>();
    scan_phase2<<<NBLK, 256>>>();
    build_perm<<<EE / 256, 256>>>(src, dstp, et);

    // ---- layer 1 ----
    gemm_tc<<<gblocks, 256, GEMM_SMEM>>>(x, bias1, 0);
    agg_edges<<<(NN * 32 + 255) / 256, 256>>>(batch, 0);

    // ---- layer 2 ----
    gemm_tc<<<gblocks, 256, GEMM_SMEM>>>(x, bias2, 1);
    agg_edges<<<(NN * 32 + 255) / 256, 256>>>(batch, 1);   // fused relu + pool

    // ---- classifier ----
    classify<<<(GG * CC + 255) / 256, 256>>>(batch, clw, clb, out);
}

// round 14
// speedup vs baseline: 1.0564x; 1.0421x over previous
#include <cuda_runtime.h>
#include <cuda_fp16.h>
#include <cstdint>

#define NN 50000
#define EE 800000
#define RR 4
#define CC 4
#define GG 512
#define NBLK 196          // (NN + 255) / 256

// ---------------- device scratch (static, no allocation) ----------------
// NOTE: buffers are self-cleaning: each accumulator is re-zeroed by its last
// reader inside the graph, so every replay starts from a clean state.
__device__ float g_Wt1[320 * 64];                   // Wt[c][k], tf32-rounded bits
__device__ float g_Wt2[320 * 64];
__device__ __half2 g_h2[(size_t)RR * NN * 32];      // per-relation messages, fp16
__device__ float g_agg1[(size_t)NN * 64];           // self+bias then += scaled messages
__device__ float g_agg2[(size_t)NN * 64];           // layer2 self
__device__ float g_cnt[RR * NN];                    // zeroed by scan_phase1 after read
__device__ float g_inv[RR * NN];
__device__ int   g_deg[NN];
__device__ int   g_bsum[NBLK];
__device__ int   g_off[NN + 1];
__device__ int   g_fill[NN];                        // zeroed by layer-0 agg_edges
__device__ unsigned g_eperm[EE];                    // (et<<16)|src grouped by dst
__device__ float g_pool[GG * 64];                   // zeroed by classify after read

__device__ __forceinline__ uint32_t f2tf32(float x) {
    uint32_t u;
    asm("cvt.rna.tf32.f32 %0, %1;" : "=r"(u) : "f"(x));
    return u;
}

// ---------------- init: weight prep only (accumulators self-clean) -------------
__global__ void init_w(const float* __restrict__ b1, const float* __restrict__ c1,
                       const float* __restrict__ r1, const float* __restrict__ b2,
                       const float* __restrict__ c2, const float* __restrict__ r2) {
    int w = blockIdx.x * blockDim.x + threadIdx.x;
    if (w >= 2 * 320 * 64) return;
    int layer = w / 20480;
    int i = w % 20480;
    int c = i / 64;
    int k = i % 64;
    const float* basis = layer ? b2 : b1;
    const float* comp  = layer ? c2 : c1;
    const float* root  = layer ? r2 : r1;
    float v;
    if (c < 256) {
        int r = c >> 6, o = c & 63;
        v = 0.f;
#pragma unroll
        for (int b = 0; b < 4; b++)
            v += comp[r * 4 + b] * basis[((size_t)b * 64 + k) * 64 + o];
    } else {
        v = root[k * 64 + (c - 256)];
    }
    (layer ? g_Wt2 : g_Wt1)[c * 64 + k] = __uint_as_float(f2tf32(v));
}

// ---------------- per-(relation,dst) edge counts ----------------
__global__ void count_edges(const int* __restrict__ dst, const int* __restrict__ et) {
    int e = blockIdx.x * blockDim.x + threadIdx.x;
    if (e >= EE) return;
    atomicAdd(&g_cnt[et[e] * NN + dst[e]], 1.0f);
}

// ---------------- scan phase 1: inv+deg from cnt, per-block sums; cleans cnt ---
__global__ void __launch_bounds__(256) scan_phase1() {
    __shared__ int sh[256];
    int t = threadIdx.x;
    int i = blockIdx.x * 256 + t;
    int d = 0;
    if (i < NN) {
        float c0 = g_cnt[i], c1 = g_cnt[NN + i], c2 = g_cnt[2 * NN + i], c3 = g_cnt[3 * NN + i];
        g_inv[i]          = 1.0f / fmaxf(c0, 1.f);
        g_inv[NN + i]     = 1.0f / fmaxf(c1, 1.f);
        g_inv[2 * NN + i] = 1.0f / fmaxf(c2, 1.f);
        g_inv[3 * NN + i] = 1.0f / fmaxf(c3, 1.f);
        d = (int)(c0 + c1 + c2 + c3);
        g_deg[i] = d;
        // self-clean for next replay (sole reader of g_cnt)
        g_cnt[i] = 0.f;
        g_cnt[NN + i] = 0.f;
        g_cnt[2 * NN + i] = 0.f;
        g_cnt[3 * NN + i] = 0.f;
    }
    sh[t] = d;
    __syncthreads();
#pragma unroll
    for (int s = 128; s > 0; s >>= 1) {
        if (t < s) sh[t] += sh[t + s];
        __syncthreads();
    }
    if (t == 0) g_bsum[blockIdx.x] = sh[0];
}

// ---------------- scan phase 2: block offset + intra-block scan ----------------
__global__ void __launch_bounds__(256) scan_phase2() {
    __shared__ int sh[256];
    int bid = blockIdx.x, t = threadIdx.x;

    sh[t] = (t < bid) ? g_bsum[t] : 0;      // bid < NBLK <= 256
    __syncthreads();
#pragma unroll
    for (int s = 128; s > 0; s >>= 1) {
        if (t < s) sh[t] += sh[t + s];
        __syncthreads();
    }
    int blockOff = sh[0];
    __syncthreads();

    int i = bid * 256 + t;
    int v = (i < NN) ? g_deg[i] : 0;
    sh[t] = v;
    __syncthreads();
#pragma unroll
    for (int s = 1; s < 256; s <<= 1) {
        int x = (t >= s) ? sh[t - s] : 0;
        __syncthreads();
        sh[t] += x;
        __syncthreads();
    }
    int excl = sh[t] - v;
    if (i <= NN) g_off[i] = blockOff + excl;
}

__global__ void build_perm(const int* __restrict__ src, const int* __restrict__ dst,
                           const int* __restrict__ et) {
    int e = blockIdx.x * blockDim.x + threadIdx.x;
    if (e >= EE) return;
    int d = dst[e];
    int pos = g_off[d] + atomicAdd(&g_fill[d], 1);
    g_eperm[pos] = ((unsigned)et[e] << 16) | (unsigned)src[e];
}

// ================= tf32 mma.sync GEMM: [128,64] @ [64,320] per CTA =================
#define SPAD 68
#define AS_FLOATS (128 * SPAD)
#define BS_FLOATS (320 * SPAD)
#define GEMM_SMEM ((AS_FLOATS + BS_FLOATS) * 4)

__global__ void __launch_bounds__(256)
gemm_tc(const float* __restrict__ Xin, const float* __restrict__ bias, int layer) {
    extern __shared__ float smem[];
    float* As = smem;                  // [128][68]
    float* Bs = smem + AS_FLOATS;      // [320][68]
    __shared__ float s_bias[64];

    const float* X = layer ? g_agg1 : Xin;
    const float* W = layer ? g_Wt2 : g_Wt1;
    float* aggOut = layer ? g_agg2 : g_agg1;
    const bool doRelu = (layer == 1);

    int t = threadIdx.x;
    int wid = t >> 5, lane = t & 31;
    int nodeBase = blockIdx.x * 128;
    if (t < 64) s_bias[t] = bias[t];

#pragma unroll
    for (int i = 0; i < 8; i++) {
        int f = t + i * 256;
        int row = f >> 4;
        int k4 = (f & 15) << 2;
        int gn = nodeBase + row;
        float4 v = make_float4(0.f, 0.f, 0.f, 0.f);
        if (gn < NN) v = *(const float4*)(X + (size_t)gn * 64 + k4);
        if (doRelu) {
            v.x = fmaxf(v.x, 0.f); v.y = fmaxf(v.y, 0.f);
            v.z = fmaxf(v.z, 0.f); v.w = fmaxf(v.w, 0.f);
        }
        float* d = As + row * SPAD + k4;
        d[0] = __uint_as_float(f2tf32(v.x));
        d[1] = __uint_as_float(f2tf32(v.y));
        d[2] = __uint_as_float(f2tf32(v.z));
        d[3] = __uint_as_float(f2tf32(v.w));
    }
#pragma unroll
    for (int i = 0; i < 20; i++) {
        int f = t + i * 256;
        int row = f >> 4;
        int k4 = (f & 15) << 2;
        *(float4*)(Bs + row * SPAD + k4) = *(const float4*)(W + (size_t)row * 64 + k4);
    }
    __syncthreads();

    int qrow = lane >> 2;
    int qcol = lane & 3;
    const float* Abase = As + (wid * 16 + qrow) * SPAD + qcol;
    const float* Bbase = Bs + qrow * SPAD + qcol;

#pragma unroll
    for (int j = 0; j < 5; j++) {
        float c[8][4];
#pragma unroll
        for (int nt = 0; nt < 8; nt++)
#pragma unroll
            for (int q = 0; q < 4; q++) c[nt][q] = 0.f;

#pragma unroll
        for (int ks = 0; ks < 8; ks++) {
            int k = ks * 8;
            uint32_t a0 = __float_as_uint(Abase[k]);
            uint32_t a1 = __float_as_uint(Abase[8 * SPAD + k]);
            uint32_t a2 = __float_as_uint(Abase[k + 4]);
            uint32_t a3 = __float_as_uint(Abase[8 * SPAD + k + 4]);
#pragma unroll
            for (int nt = 0; nt < 8; nt++) {
                const float* bp = Bbase + (j * 64 + nt * 8) * SPAD + k;
                uint32_t b0 = __float_as_uint(bp[0]);
                uint32_t b1 = __float_as_uint(bp[4]);
                asm volatile(
                    "mma.sync.aligned.m16n8k8.row.col.f32.tf32.tf32.f32 "
                    "{%0,%1,%2,%3}, {%4,%5,%6,%7}, {%8,%9}, {%0,%1,%2,%3};"
                    : "+f"(c[nt][0]), "+f"(c[nt][1]), "+f"(c[nt][2]), "+f"(c[nt][3])
                    : "r"(a0), "r"(a1), "r"(a2), "r"(a3), "r"(b0), "r"(b1));
            }
        }

        int node0 = nodeBase + wid * 16 + qrow;
        int node1 = node0 + 8;
        if (j < 4) {
            __half2* h0 = g_h2 + ((size_t)j * NN + node0) * 32 + qcol;
            __half2* h1 = g_h2 + ((size_t)j * NN + node1) * 32 + qcol;
#pragma unroll
            for (int nt = 0; nt < 8; nt++) {
                if (node0 < NN) h0[nt * 4] = __floats2half2_rn(c[nt][0], c[nt][1]);
                if (node1 < NN) h1[nt * 4] = __floats2half2_rn(c[nt][2], c[nt][3]);
            }
        } else {
            float* a0p = aggOut + (size_t)node0 * 64 + qcol * 2;
            float* a1p = aggOut + (size_t)node1 * 64 + qcol * 2;
#pragma unroll
            for (int nt = 0; nt < 8; nt++) {
                float bx = s_bias[nt * 8 + qcol * 2];
                float by = s_bias[nt * 8 + qcol * 2 + 1];
                if (node0 < NN) *(float2*)(a0p + nt * 8) = make_float2(c[nt][0] + bx, c[nt][1] + by);
                if (node1 < NN) *(float2*)(a1p + nt * 8) = make_float2(c[nt][2] + bx, c[nt][3] + by);
            }
        }
    }
}

// ---------------- segmented aggregation: exact R11 mainloop ----------------
// One warp per dst, 4-way unroll, per-edge independent g_inv loads (they overlap
// the gather chain; SEL-from-registers variants measured slower in R12/R13).
__global__ void __launch_bounds__(256) agg_edges(const int* __restrict__ batch, int layer) {
    int w = (blockIdx.x * blockDim.x + threadIdx.x) >> 5;
    if (w >= NN) return;
    int lane = threadIdx.x & 31;
    if (layer == 0 && lane == 0) g_fill[w] = 0;       // self-clean for next replay
    int beg = g_off[w], end = g_off[w + 1];
    float* agg = (layer ? g_agg2 : g_agg1) + (size_t)w * 64 + lane * 2;
    float2 a0 = *(float2*)agg;                         // self + bias from GEMM
    float2 a1 = make_float2(0.f, 0.f);
    float2 a2 = make_float2(0.f, 0.f);
    float2 a3 = make_float2(0.f, 0.f);

    const __half2* hb = g_h2 + lane;

    int e = beg;
    for (; e + 3 < end; e += 4) {
        unsigned p0 = g_eperm[e], p1 = g_eperm[e + 1];
        unsigned p2 = g_eperm[e + 2], p3 = g_eperm[e + 3];
        float i0 = g_inv[(p0 >> 16) * NN + w];
        float i1 = g_inv[(p1 >> 16) * NN + w];
        float i2 = g_inv[(p2 >> 16) * NN + w];
        float i3 = g_inv[(p3 >> 16) * NN + w];
        float2 v0 = __half22float2(hb[(((size_t)(p0 >> 16)) * NN + (p0 & 0xFFFF)) * 32]);
        float2 v1 = __half22float2(hb[(((size_t)(p1 >> 16)) * NN + (p1 & 0xFFFF)) * 32]);
        float2 v2 = __half22float2(hb[(((size_t)(p2 >> 16)) * NN + (p2 & 0xFFFF)) * 32]);
        float2 v3 = __half22float2(hb[(((size_t)(p3 >> 16)) * NN + (p3 & 0xFFFF)) * 32]);
        a0.x += v0.x * i0; a0.y += v0.y * i0;
        a1.x += v1.x * i1; a1.y += v1.y * i1;
        a2.x += v2.x * i2; a2.y += v2.y * i2;
        a3.x += v3.x * i3; a3.y += v3.y * i3;
    }
    for (; e < end; e++) {
        unsigned p = g_eperm[e];
        float iv = g_inv[(p >> 16) * NN + w];
        float2 v = __half22float2(hb[(((size_t)(p >> 16)) * NN + (p & 0xFFFF)) * 32]);
        a0.x += v.x * iv; a0.y += v.y * iv;
    }
    a0.x += a1.x + a2.x + a3.x;
    a0.y += a1.y + a2.y + a3.y;

    if (layer == 0) {
        *(float2*)agg = a0;                            // relu applied by layer-2 gemm load
    } else {
        float rx = fmaxf(a0.x, 0.f);
        float ry = fmaxf(a0.y, 0.f);
        float* p = g_pool + batch[w] * 64 + lane * 2;
        asm volatile("red.global.add.v2.f32 [%0], {%1,%2};"
                     :: "l"(p), "f"(rx), "f"(ry) : "memory");
    }
}

// ---------------- classifier; zeros g_pool after reading (self-clean) ----------
// 8 blocks x 256 threads = 2048 = GG*CC exactly; block b owns graphs [b*64, b*64+64)
// and therefore pool rows read only by its own threads.
__global__ void __launch_bounds__(256) classify(const int* __restrict__ batch,
                                                const float* __restrict__ w,
                                                const float* __restrict__ b,
                                                float* __restrict__ out) {
    int t = blockIdx.x * blockDim.x + threadIdx.x;
    int g = t / CC, c = t % CC;
    int lo = 0, hi = NN;
    while (lo < hi) { int m = (lo + hi) >> 1; if (batch[m] < g) lo = m + 1; else hi = m; }
    int lo2 = lo, hi2 = NN;
    while (lo2 < hi2) { int m = (lo2 + hi2) >> 1; if (batch[m] < g + 1) lo2 = m + 1; else hi2 = m; }
    float inv = 1.f / fmaxf((float)(lo2 - lo), 1.f);
    float acc = b[c];
#pragma unroll
    for (int k = 0; k < 64; k++)
        acc += g_pool[g * 64 + k] * inv * w[k * CC + c];
    out[t] = acc;

    __syncthreads();
    // zero this block's pool region (64 graphs x 64 ch = 4096 floats)
    float* pz = g_pool + blockIdx.x * 64 * 64;
    for (int i = threadIdx.x; i < 64 * 64; i += 256) pz[i] = 0.f;
}

// ---------------- launch ----------------
extern "C" void kernel_launch(void* const* d_in, const int* in_sizes, int n_in,
                              void* d_out, int out_size) {
    const float* x      = (const float*)d_in[0];
    const int*   ei     = (const int*)d_in[1];
    const int*   et     = (const int*)d_in[2];
    const int*   batch  = (const int*)d_in[3];
    const float* basis1 = (const float*)d_in[4];
    const float* comp1  = (const float*)d_in[5];
    const float* root1  = (const float*)d_in[6];
    const float* bias1  = (const float*)d_in[7];
    const float* basis2 = (const float*)d_in[8];
    const float* comp2  = (const float*)d_in[9];
    const float* root2  = (const float*)d_in[10];
    const float* bias2  = (const float*)d_in[11];
    const float* clw    = (const float*)d_in[12];
    const float* clb    = (const float*)d_in[13];
    float* out = (float*)d_out;

    const int* src = ei;
    const int* dstp = ei + EE;

    static int inited = 0;
    if (!inited) {
        cudaFuncSetAttribute(gemm_tc, cudaFuncAttributeMaxDynamicSharedMemorySize,
                             GEMM_SMEM);
        inited = 1;
    }

    int gblocks = (NN + 127) / 128;   // 391

    // ---- preprocessing ----
    init_w<<<160, 256>>>(basis1, comp1, root1, basis2, comp2, root2);
    count_edges<<<EE / 256, 256>>>(dstp, et);
    scan_phase1<<<NBLK, 256>>>();
    scan_phase2<<<NBLK, 256>>>();
    build_perm<<<EE / 256, 256>>>(src, dstp, et);

    // ---- layer 1 ----
    gemm_tc<<<gblocks, 256, GEMM_SMEM>>>(x, bias1, 0);
    agg_edges<<<(NN * 32 + 255) / 256, 256>>>(batch, 0);

    // ---- layer 2 ----
    gemm_tc<<<gblocks, 256, GEMM_SMEM>>>(x, bias2, 1);
    agg_edges<<<(NN * 32 + 255) / 256, 256>>>(batch, 1);   // fused relu + pool

    // ---- classifier ----
    classify<<<(GG * CC) / 256, 256>>>(batch, clw, clb, out);
}

// round 15
// speedup vs baseline: 1.0896x; 1.0314x over previous
#include <cuda_runtime.h>
#include <cuda_fp16.h>
#include <cstdint>

#define NN 50000
#define EE 800000
#define RR 4
#define CC 4
#define GG 512
#define NBLK 196          // (NN + 255) / 256

// ---------------- device scratch (static, no allocation) ----------------
// Self-cleaning: each accumulator is re-zeroed by its last reader in the graph.
__device__ float g_Wt1[320 * 64];                   // Wt[c][k], tf32-rounded bits
__device__ float g_Wt2[320 * 64];
__device__ __half2 g_h2[(size_t)RR * NN * 32];      // per-relation messages, fp16
__device__ float g_agg1[(size_t)NN * 64];           // self+bias then += scaled messages
__device__ float g_agg2[(size_t)NN * 64];           // layer2 self
__device__ float g_cnt[RR * NN];                    // zeroed by scan_phase1 after read
__device__ float g_inv[RR * NN];
__device__ int   g_deg[NN];
__device__ int   g_bsum[NBLK];
__device__ int   g_off[NN + 1];
__device__ int   g_fill[NN];                        // zeroed by layer-0 agg_edges
__device__ uint2 g_eperm2[EE];                      // (inv_fp32, (et<<16)|src), by dst
__device__ float g_pool[GG * 64];                   // zeroed by classify after read

__device__ __forceinline__ uint32_t f2tf32(float x) {
    uint32_t u;
    asm("cvt.rna.tf32.f32 %0, %1;" : "=r"(u) : "f"(x));
    return u;
}

// ---------------- init: weight prep only ----------------
__global__ void init_w(const float* __restrict__ b1, const float* __restrict__ c1,
                       const float* __restrict__ r1, const float* __restrict__ b2,
                       const float* __restrict__ c2, const float* __restrict__ r2) {
    int w = blockIdx.x * blockDim.x + threadIdx.x;
    if (w >= 2 * 320 * 64) return;
    int layer = w / 20480;
    int i = w % 20480;
    int c = i / 64;
    int k = i % 64;
    const float* basis = layer ? b2 : b1;
    const float* comp  = layer ? c2 : c1;
    const float* root  = layer ? r2 : r1;
    float v;
    if (c < 256) {
        int r = c >> 6, o = c & 63;
        v = 0.f;
#pragma unroll
        for (int b = 0; b < 4; b++)
            v += comp[r * 4 + b] * basis[((size_t)b * 64 + k) * 64 + o];
    } else {
        v = root[k * 64 + (c - 256)];
    }
    (layer ? g_Wt2 : g_Wt1)[c * 64 + k] = __uint_as_float(f2tf32(v));
}

// ---------------- per-(relation,dst) edge counts ----------------
__global__ void count_edges(const int* __restrict__ dst, const int* __restrict__ et) {
    int e = blockIdx.x * blockDim.x + threadIdx.x;
    if (e >= EE) return;
    atomicAdd(&g_cnt[et[e] * NN + dst[e]], 1.0f);
}

// ---------------- scan phase 1: inv+deg from cnt, per-block sums; cleans cnt ---
__global__ void __launch_bounds__(256) scan_phase1() {
    __shared__ int sh[256];
    int t = threadIdx.x;
    int i = blockIdx.x * 256 + t;
    int d = 0;
    if (i < NN) {
        float c0 = g_cnt[i], c1 = g_cnt[NN + i], c2 = g_cnt[2 * NN + i], c3 = g_cnt[3 * NN + i];
        g_inv[i]          = 1.0f / fmaxf(c0, 1.f);
        g_inv[NN + i]     = 1.0f / fmaxf(c1, 1.f);
        g_inv[2 * NN + i] = 1.0f / fmaxf(c2, 1.f);
        g_inv[3 * NN + i] = 1.0f / fmaxf(c3, 1.f);
        d = (int)(c0 + c1 + c2 + c3);
        g_deg[i] = d;
        g_cnt[i] = 0.f;
        g_cnt[NN + i] = 0.f;
        g_cnt[2 * NN + i] = 0.f;
        g_cnt[3 * NN + i] = 0.f;
    }
    sh[t] = d;
    __syncthreads();
#pragma unroll
    for (int s = 128; s > 0; s >>= 1) {
        if (t < s) sh[t] += sh[t + s];
        __syncthreads();
    }
    if (t == 0) g_bsum[blockIdx.x] = sh[0];
}

// ---------------- scan phase 2: block offset + intra-block scan ----------------
__global__ void __launch_bounds__(256) scan_phase2() {
    __shared__ int sh[256];
    int bid = blockIdx.x, t = threadIdx.x;

    sh[t] = (t < bid) ? g_bsum[t] : 0;      // bid < NBLK <= 256
    __syncthreads();
#pragma unroll
    for (int s = 128; s > 0; s >>= 1) {
        if (t < s) sh[t] += sh[t + s];
        __syncthreads();
    }
    int blockOff = sh[0];
    __syncthreads();

    int i = bid * 256 + t;
    int v = (i < NN) ? g_deg[i] : 0;
    sh[t] = v;
    __syncthreads();
#pragma unroll
    for (int s = 1; s < 256; s <<= 1) {
        int x = (t >= s) ? sh[t - s] : 0;
        __syncthreads();
        sh[t] += x;
        __syncthreads();
    }
    int excl = sh[t] - v;
    if (i <= NN) g_off[i] = blockOff + excl;
}

// ---------------- build permutation with baked-in scale ----------------
__global__ void build_perm(const int* __restrict__ src, const int* __restrict__ dst,
                           const int* __restrict__ et) {
    int e = blockIdx.x * blockDim.x + threadIdx.x;
    if (e >= EE) return;
    int d = dst[e];
    int r = et[e];
    int pos = g_off[d] + atomicAdd(&g_fill[d], 1);
    g_eperm2[pos] = make_uint2(__float_as_uint(g_inv[r * NN + d]),
                               ((unsigned)r << 16) | (unsigned)src[e]);
}

// ================= tf32 mma.sync GEMM: [128,64] @ [64,320] per CTA =================
#define SPAD 68
#define AS_FLOATS (128 * SPAD)
#define BS_FLOATS (320 * SPAD)
#define GEMM_SMEM ((AS_FLOATS + BS_FLOATS) * 4)

__global__ void __launch_bounds__(256)
gemm_tc(const float* __restrict__ Xin, const float* __restrict__ bias, int layer) {
    extern __shared__ float smem[];
    float* As = smem;                  // [128][68]
    float* Bs = smem + AS_FLOATS;      // [320][68]
    __shared__ float s_bias[64];

    const float* X = layer ? g_agg1 : Xin;
    const float* W = layer ? g_Wt2 : g_Wt1;
    float* aggOut = layer ? g_agg2 : g_agg1;
    const bool doRelu = (layer == 1);

    int t = threadIdx.x;
    int wid = t >> 5, lane = t & 31;
    int nodeBase = blockIdx.x * 128;
    if (t < 64) s_bias[t] = bias[t];

#pragma unroll
    for (int i = 0; i < 8; i++) {
        int f = t + i * 256;
        int row = f >> 4;
        int k4 = (f & 15) << 2;
        int gn = nodeBase + row;
        float4 v = make_float4(0.f, 0.f, 0.f, 0.f);
        if (gn < NN) v = *(const float4*)(X + (size_t)gn * 64 + k4);
        if (doRelu) {
            v.x = fmaxf(v.x, 0.f); v.y = fmaxf(v.y, 0.f);
            v.z = fmaxf(v.z, 0.f); v.w = fmaxf(v.w, 0.f);
        }
        float* d = As + row * SPAD + k4;
        d[0] = __uint_as_float(f2tf32(v.x));
        d[1] = __uint_as_float(f2tf32(v.y));
        d[2] = __uint_as_float(f2tf32(v.z));
        d[3] = __uint_as_float(f2tf32(v.w));
    }
#pragma unroll
    for (int i = 0; i < 20; i++) {
        int f = t + i * 256;
        int row = f >> 4;
        int k4 = (f & 15) << 2;
        *(float4*)(Bs + row * SPAD + k4) = *(const float4*)(W + (size_t)row * 64 + k4);
    }
    __syncthreads();

    int qrow = lane >> 2;
    int qcol = lane & 3;
    const float* Abase = As + (wid * 16 + qrow) * SPAD + qcol;
    const float* Bbase = Bs + qrow * SPAD + qcol;

#pragma unroll
    for (int j = 0; j < 5; j++) {
        float c[8][4];
#pragma unroll
        for (int nt = 0; nt < 8; nt++)
#pragma unroll
            for (int q = 0; q < 4; q++) c[nt][q] = 0.f;

#pragma unroll
        for (int ks = 0; ks < 8; ks++) {
            int k = ks * 8;
            uint32_t a0 = __float_as_uint(Abase[k]);
            uint32_t a1 = __float_as_uint(Abase[8 * SPAD + k]);
            uint32_t a2 = __float_as_uint(Abase[k + 4]);
            uint32_t a3 = __float_as_uint(Abase[8 * SPAD + k + 4]);
#pragma unroll
            for (int nt = 0; nt < 8; nt++) {
                const float* bp = Bbase + (j * 64 + nt * 8) * SPAD + k;
                uint32_t b0 = __float_as_uint(bp[0]);
                uint32_t b1 = __float_as_uint(bp[4]);
                asm volatile(
                    "mma.sync.aligned.m16n8k8.row.col.f32.tf32.tf32.f32 "
                    "{%0,%1,%2,%3}, {%4,%5,%6,%7}, {%8,%9}, {%0,%1,%2,%3};"
                    : "+f"(c[nt][0]), "+f"(c[nt][1]), "+f"(c[nt][2]), "+f"(c[nt][3])
                    : "r"(a0), "r"(a1), "r"(a2), "r"(a3), "r"(b0), "r"(b1));
            }
        }

        int node0 = nodeBase + wid * 16 + qrow;
        int node1 = node0 + 8;
        if (j < 4) {
            __half2* h0 = g_h2 + ((size_t)j * NN + node0) * 32 + qcol;
            __half2* h1 = g_h2 + ((size_t)j * NN + node1) * 32 + qcol;
#pragma unroll
            for (int nt = 0; nt < 8; nt++) {
                if (node0 < NN) h0[nt * 4] = __floats2half2_rn(c[nt][0], c[nt][1]);
                if (node1 < NN) h1[nt * 4] = __floats2half2_rn(c[nt][2], c[nt][3]);
            }
        } else {
            float* a0p = aggOut + (size_t)node0 * 64 + qcol * 2;
            float* a1p = aggOut + (size_t)node1 * 64 + qcol * 2;
#pragma unroll
            for (int nt = 0; nt < 8; nt++) {
                float bx = s_bias[nt * 8 + qcol * 2];
                float by = s_bias[nt * 8 + qcol * 2 + 1];
                if (node0 < NN) *(float2*)(a0p + nt * 8) = make_float2(c[nt][0] + bx, c[nt][1] + by);
                if (node1 < NN) *(float2*)(a1p + nt * 8) = make_float2(c[nt][2] + bx, c[nt][3] + by);
            }
        }
    }
}

// ---------------- segmented aggregation: one warp per dst, 4-way unroll --------
// R11 chain structure, but each edge record is one LDG.64 carrying (inv, idx):
// per 4 edges: 4 independent LDG.64 + 4 gathers (was 12 LDGs).
__global__ void __launch_bounds__(256) agg_edges(const int* __restrict__ batch, int layer) {
    int w = (blockIdx.x * blockDim.x + threadIdx.x) >> 5;
    if (w >= NN) return;
    int lane = threadIdx.x & 31;
    if (layer == 0 && lane == 0) g_fill[w] = 0;       // self-clean for next replay
    int beg = g_off[w], end = g_off[w + 1];
    float* agg = (layer ? g_agg2 : g_agg1) + (size_t)w * 64 + lane * 2;
    float2 a0 = *(float2*)agg;                         // self + bias from GEMM
    float2 a1 = make_float2(0.f, 0.f);
    float2 a2 = make_float2(0.f, 0.f);
    float2 a3 = make_float2(0.f, 0.f);

    const __half2* hb = g_h2 + lane;

    int e = beg;
    for (; e + 3 < end; e += 4) {
        uint2 p0 = g_eperm2[e],     p1 = g_eperm2[e + 1];
        uint2 p2 = g_eperm2[e + 2], p3 = g_eperm2[e + 3];
        float2 v0 = __half22float2(hb[(((size_t)(p0.y >> 16)) * NN + (p0.y & 0xFFFF)) * 32]);
        float2 v1 = __half22float2(hb[(((size_t)(p1.y >> 16)) * NN + (p1.y & 0xFFFF)) * 32]);
        float2 v2 = __half22float2(hb[(((size_t)(p2.y >> 16)) * NN + (p2.y & 0xFFFF)) * 32]);
        float2 v3 = __half22float2(hb[(((size_t)(p3.y >> 16)) * NN + (p3.y & 0xFFFF)) * 32]);
        float i0 = __uint_as_float(p0.x);
        float i1 = __uint_as_float(p1.x);
        float i2 = __uint_as_float(p2.x);
        float i3 = __uint_as_float(p3.x);
        a0.x += v0.x * i0; a0.y += v0.y * i0;
        a1.x += v1.x * i1; a1.y += v1.y * i1;
        a2.x += v2.x * i2; a2.y += v2.y * i2;
        a3.x += v3.x * i3; a3.y += v3.y * i3;
    }
    for (; e < end; e++) {
        uint2 p = g_eperm2[e];
        float iv = __uint_as_float(p.x);
        float2 v = __half22float2(hb[(((size_t)(p.y >> 16)) * NN + (p.y & 0xFFFF)) * 32]);
        a0.x += v.x * iv; a0.y += v.y * iv;
    }
    a0.x += a1.x + a2.x + a3.x;
    a0.y += a1.y + a2.y + a3.y;

    if (layer == 0) {
        *(float2*)agg = a0;                            // relu applied by layer-2 gemm load
    } else {
        float rx = fmaxf(a0.x, 0.f);
        float ry = fmaxf(a0.y, 0.f);
        float* p = g_pool + batch[w] * 64 + lane * 2;
        asm volatile("red.global.add.v2.f32 [%0], {%1,%2};"
                     :: "l"(p), "f"(rx), "f"(ry) : "memory");
    }
}

// ---------------- classifier; zeros g_pool after reading (self-clean) ----------
__global__ void __launch_bounds__(256) classify(const int* __restrict__ batch,
                                                const float* __restrict__ w,
                                                const float* __restrict__ b,
                                                float* __restrict__ out) {
    int t = blockIdx.x * blockDim.x + threadIdx.x;
    int g = t / CC, c = t % CC;
    int lo = 0, hi = NN;
    while (lo < hi) { int m = (lo + hi) >> 1; if (batch[m] < g) lo = m + 1; else hi = m; }
    int lo2 = lo, hi2 = NN;
    while (lo2 < hi2) { int m = (lo2 + hi2) >> 1; if (batch[m] < g + 1) lo2 = m + 1; else hi2 = m; }
    float inv = 1.f / fmaxf((float)(lo2 - lo), 1.f);
    float acc = b[c];
#pragma unroll
    for (int k = 0; k < 64; k++)
        acc += g_pool[g * 64 + k] * inv * w[k * CC + c];
    out[t] = acc;

    __syncthreads();
    float* pz = g_pool + blockIdx.x * 64 * 64;
    for (int i = threadIdx.x; i < 64 * 64; i += 256) pz[i] = 0.f;
}

// ---------------- launch ----------------
extern "C" void kernel_launch(void* const* d_in, const int* in_sizes, int n_in,
                              void* d_out, int out_size) {
    const float* x      = (const float*)d_in[0];
    const int*   ei     = (const int*)d_in[1];
    const int*   et     = (const int*)d_in[2];
    const int*   batch  = (const int*)d_in[3];
    const float* basis1 = (const float*)d_in[4];
    const float* comp1  = (const float*)d_in[5];
    const float* root1  = (const float*)d_in[6];
    const float* bias1  = (const float*)d_in[7];
    const float* basis2 = (const float*)d_in[8];
    const float* comp2  = (const float*)d_in[9];
    const float* root2  = (const float*)d_in[10];
    const float* bias2  = (const float*)d_in[11];
    const float* clw    = (const float*)d_in[12];
    const float* clb    = (const float*)d_in[13];
    float* out = (float*)d_out;

    const int* src = ei;
    const int* dstp = ei + EE;

    static int inited = 0;
    if (!inited) {
        cudaFuncSetAttribute(gemm_tc, cudaFuncAttributeMaxDynamicSharedMemorySize,
                             GEMM_SMEM);
        inited = 1;
    }

    int gblocks = (NN + 127) / 128;   // 391

    // ---- preprocessing ----
    init_w<<<160, 256>>>(basis1, comp1, root1, basis2, comp2, root2);
    count_edges<<<EE / 256, 256>>>(dstp, et);
    scan_phase1<<<NBLK, 256>>>();
    scan_phase2<<<NBLK, 256>>>();
    build_perm<<<EE / 256, 256>>>(src, dstp, et);

    // ---- layer 1 ----
    gemm_tc<<<gblocks, 256, GEMM_SMEM>>>(x, bias1, 0);
    agg_edges<<<(NN * 32 + 255) / 256, 256>>>(batch, 0);

    // ---- layer 2 ----
    gemm_tc<<<gblocks, 256, GEMM_SMEM>>>(x, bias2, 1);
    agg_edges<<<(NN * 32 + 255) / 256, 256>>>(batch, 1);   // fused relu + pool

    // ---- classifier ----
    classify<<<(GG * CC) / 256, 256>>>(batch, clw, clb, out);
}

// round 16
// speedup vs baseline: 1.1709x; 1.0746x over previous
#include <cuda_runtime.h>
#include <cuda_fp16.h>
#include <cstdint>

#define NN 50000
#define EE 800000
#define RR 4
#define CC 4
#define GG 512
#define NBLK 196          // (NN + 255) / 256

// ---------------- device scratch (static, no allocation) ----------------
// Self-cleaning: each accumulator is re-zeroed by its last reader in the graph.
__device__ float g_Wt1[320 * 64];                   // Wt[c][k], tf32-rounded bits
__device__ float g_Wt2[320 * 64];
__device__ __half2 g_h2[(size_t)RR * NN * 32];      // per-relation messages, fp16
__device__ float g_agg1[(size_t)NN * 64];           // self+bias then += scaled messages
__device__ float g_agg2[(size_t)NN * 64];           // layer2 self
__device__ float g_cnt[RR * NN];                    // zeroed by scan_phase1 after read
__device__ float g_inv[RR * NN];
__device__ int   g_deg[NN];
__device__ int   g_bsum[NBLK];
__device__ int   g_off[NN + 1];
__device__ int   g_fill[NN];                        // zeroed by layer-0 agg_edges
__device__ uint2 g_eperm2[EE];                      // (inv_fp32, (et<<16)|src), by dst
__device__ float g_pool[GG * 64];                   // zeroed by classify after read

__device__ __forceinline__ uint32_t f2tf32(float x) {
    uint32_t u;
    asm("cvt.rna.tf32.f32 %0, %1;" : "=r"(u) : "f"(x));
    return u;
}

// ---------------- init: weight prep only ----------------
__global__ void init_w(const float* __restrict__ b1, const float* __restrict__ c1,
                       const float* __restrict__ r1, const float* __restrict__ b2,
                       const float* __restrict__ c2, const float* __restrict__ r2) {
    int w = blockIdx.x * blockDim.x + threadIdx.x;
    if (w >= 2 * 320 * 64) return;
    int layer = w / 20480;
    int i = w % 20480;
    int c = i / 64;
    int k = i % 64;
    const float* basis = layer ? b2 : b1;
    const float* comp  = layer ? c2 : c1;
    const float* root  = layer ? r2 : r1;
    float v;
    if (c < 256) {
        int r = c >> 6, o = c & 63;
        v = 0.f;
#pragma unroll
        for (int b = 0; b < 4; b++)
            v += comp[r * 4 + b] * basis[((size_t)b * 64 + k) * 64 + o];
    } else {
        v = root[k * 64 + (c - 256)];
    }
    (layer ? g_Wt2 : g_Wt1)[c * 64 + k] = __uint_as_float(f2tf32(v));
}

// ---------------- per-(relation,dst) edge counts ----------------
__global__ void count_edges(const int* __restrict__ dst, const int* __restrict__ et) {
    int e = blockIdx.x * blockDim.x + threadIdx.x;
    if (e >= EE) return;
    atomicAdd(&g_cnt[et[e] * NN + dst[e]], 1.0f);
}

// ---------------- scan phase 1: inv+deg from cnt, per-block sums; cleans cnt ---
__global__ void __launch_bounds__(256) scan_phase1() {
    __shared__ int sh[256];
    int t = threadIdx.x;
    int i = blockIdx.x * 256 + t;
    int d = 0;
    if (i < NN) {
        float c0 = g_cnt[i], c1 = g_cnt[NN + i], c2 = g_cnt[2 * NN + i], c3 = g_cnt[3 * NN + i];
        g_inv[i]          = 1.0f / fmaxf(c0, 1.f);
        g_inv[NN + i]     = 1.0f / fmaxf(c1, 1.f);
        g_inv[2 * NN + i] = 1.0f / fmaxf(c2, 1.f);
        g_inv[3 * NN + i] = 1.0f / fmaxf(c3, 1.f);
        d = (int)(c0 + c1 + c2 + c3);
        g_deg[i] = d;
        g_cnt[i] = 0.f;
        g_cnt[NN + i] = 0.f;
        g_cnt[2 * NN + i] = 0.f;
        g_cnt[3 * NN + i] = 0.f;
    }
    sh[t] = d;
    __syncthreads();
#pragma unroll
    for (int s = 128; s > 0; s >>= 1) {
        if (t < s) sh[t] += sh[t + s];
        __syncthreads();
    }
    if (t == 0) g_bsum[blockIdx.x] = sh[0];
}

// ---------------- scan phase 2: block offset + intra-block scan ----------------
__global__ void __launch_bounds__(256) scan_phase2() {
    __shared__ int sh[256];
    int bid = blockIdx.x, t = threadIdx.x;

    sh[t] = (t < bid) ? g_bsum[t] : 0;      // bid < NBLK <= 256
    __syncthreads();
#pragma unroll
    for (int s = 128; s > 0; s >>= 1) {
        if (t < s) sh[t] += sh[t + s];
        __syncthreads();
    }
    int blockOff = sh[0];
    __syncthreads();

    int i = bid * 256 + t;
    int v = (i < NN) ? g_deg[i] : 0;
    sh[t] = v;
    __syncthreads();
#pragma unroll
    for (int s = 1; s < 256; s <<= 1) {
        int x = (t >= s) ? sh[t - s] : 0;
        __syncthreads();
        sh[t] += x;
        __syncthreads();
    }
    int excl = sh[t] - v;
    if (i <= NN) g_off[i] = blockOff + excl;
}

// ---------------- build permutation with baked-in scale ----------------
__global__ void build_perm(const int* __restrict__ src, const int* __restrict__ dst,
                           const int* __restrict__ et) {
    int e = blockIdx.x * blockDim.x + threadIdx.x;
    if (e >= EE) return;
    int d = dst[e];
    int r = et[e];
    int pos = g_off[d] + atomicAdd(&g_fill[d], 1);
    g_eperm2[pos] = make_uint2(__float_as_uint(g_inv[r * NN + d]),
                               ((unsigned)r << 16) | (unsigned)src[e]);
}

// ================= tf32 mma.sync GEMM: [128,64] @ [64,320] per CTA =================
#define SPAD 68
#define AS_FLOATS (128 * SPAD)
#define BS_FLOATS (320 * SPAD)
#define GEMM_SMEM ((AS_FLOATS + BS_FLOATS) * 4)

__global__ void __launch_bounds__(256)
gemm_tc(const float* __restrict__ Xin, const float* __restrict__ bias, int layer) {
    extern __shared__ float smem[];
    float* As = smem;                  // [128][68]
    float* Bs = smem + AS_FLOATS;      // [320][68]
    __shared__ float s_bias[64];

    const float* X = layer ? g_agg1 : Xin;
    const float* W = layer ? g_Wt2 : g_Wt1;
    float* aggOut = layer ? g_agg2 : g_agg1;
    const bool doRelu = (layer == 1);

    int t = threadIdx.x;
    int wid = t >> 5, lane = t & 31;
    int nodeBase = blockIdx.x * 128;
    if (t < 64) s_bias[t] = bias[t];

#pragma unroll
    for (int i = 0; i < 8; i++) {
        int f = t + i * 256;
        int row = f >> 4;
        int k4 = (f & 15) << 2;
        int gn = nodeBase + row;
        float4 v = make_float4(0.f, 0.f, 0.f, 0.f);
        if (gn < NN) v = *(const float4*)(X + (size_t)gn * 64 + k4);
        if (doRelu) {
            v.x = fmaxf(v.x, 0.f); v.y = fmaxf(v.y, 0.f);
            v.z = fmaxf(v.z, 0.f); v.w = fmaxf(v.w, 0.f);
        }
        float* d = As + row * SPAD + k4;
        d[0] = __uint_as_float(f2tf32(v.x));
        d[1] = __uint_as_float(f2tf32(v.y));
        d[2] = __uint_as_float(f2tf32(v.z));
        d[3] = __uint_as_float(f2tf32(v.w));
    }
#pragma unroll
    for (int i = 0; i < 20; i++) {
        int f = t + i * 256;
        int row = f >> 4;
        int k4 = (f & 15) << 2;
        *(float4*)(Bs + row * SPAD + k4) = *(const float4*)(W + (size_t)row * 64 + k4);
    }
    __syncthreads();

    int qrow = lane >> 2;
    int qcol = lane & 3;
    const float* Abase = As + (wid * 16 + qrow) * SPAD + qcol;
    const float* Bbase = Bs + qrow * SPAD + qcol;

#pragma unroll
    for (int j = 0; j < 5; j++) {
        float c[8][4];
#pragma unroll
        for (int nt = 0; nt < 8; nt++)
#pragma unroll
            for (int q = 0; q < 4; q++) c[nt][q] = 0.f;

#pragma unroll
        for (int ks = 0; ks < 8; ks++) {
            int k = ks * 8;
            uint32_t a0 = __float_as_uint(Abase[k]);
            uint32_t a1 = __float_as_uint(Abase[8 * SPAD + k]);
            uint32_t a2 = __float_as_uint(Abase[k + 4]);
            uint32_t a3 = __float_as_uint(Abase[8 * SPAD + k + 4]);
#pragma unroll
            for (int nt = 0; nt < 8; nt++) {
                const float* bp = Bbase + (j * 64 + nt * 8) * SPAD + k;
                uint32_t b0 = __float_as_uint(bp[0]);
                uint32_t b1 = __float_as_uint(bp[4]);
                asm volatile(
                    "mma.sync.aligned.m16n8k8.row.col.f32.tf32.tf32.f32 "
                    "{%0,%1,%2,%3}, {%4,%5,%6,%7}, {%8,%9}, {%0,%1,%2,%3};"
                    : "+f"(c[nt][0]), "+f"(c[nt][1]), "+f"(c[nt][2]), "+f"(c[nt][3])
                    : "r"(a0), "r"(a1), "r"(a2), "r"(a3), "r"(b0), "r"(b1));
            }
        }

        int node0 = nodeBase + wid * 16 + qrow;
        int node1 = node0 + 8;
        if (j < 4) {
            __half2* h0 = g_h2 + ((size_t)j * NN + node0) * 32 + qcol;
            __half2* h1 = g_h2 + ((size_t)j * NN + node1) * 32 + qcol;
#pragma unroll
            for (int nt = 0; nt < 8; nt++) {
                if (node0 < NN) h0[nt * 4] = __floats2half2_rn(c[nt][0], c[nt][1]);
                if (node1 < NN) h1[nt * 4] = __floats2half2_rn(c[nt][2], c[nt][3]);
            }
        } else {
            float* a0p = aggOut + (size_t)node0 * 64 + qcol * 2;
            float* a1p = aggOut + (size_t)node1 * 64 + qcol * 2;
#pragma unroll
            for (int nt = 0; nt < 8; nt++) {
                float bx = s_bias[nt * 8 + qcol * 2];
                float by = s_bias[nt * 8 + qcol * 2 + 1];
                if (node0 < NN) *(float2*)(a0p + nt * 8) = make_float2(c[nt][0] + bx, c[nt][1] + by);
                if (node1 < NN) *(float2*)(a1p + nt * 8) = make_float2(c[nt][2] + bx, c[nt][3] + by);
            }
        }
    }
}

// ---------------- segmented aggregation: one warp per dst, 4-way unroll --------
__global__ void __launch_bounds__(256) agg_edges(const int* __restrict__ batch, int layer) {
    int w = (blockIdx.x * blockDim.x + threadIdx.x) >> 5;
    if (w >= NN) return;
    int lane = threadIdx.x & 31;
    if (layer == 0 && lane == 0) g_fill[w] = 0;       // self-clean for next replay
    int beg = g_off[w], end = g_off[w + 1];
    float* agg = (layer ? g_agg2 : g_agg1) + (size_t)w * 64 + lane * 2;
    float2 a0 = *(float2*)agg;                         // self + bias from GEMM
    float2 a1 = make_float2(0.f, 0.f);
    float2 a2 = make_float2(0.f, 0.f);
    float2 a3 = make_float2(0.f, 0.f);

    const __half2* hb = g_h2 + lane;

    int e = beg;
    for (; e + 3 < end; e += 4) {
        uint2 p0 = g_eperm2[e],     p1 = g_eperm2[e + 1];
        uint2 p2 = g_eperm2[e + 2], p3 = g_eperm2[e + 3];
        float2 v0 = __half22float2(hb[(((size_t)(p0.y >> 16)) * NN + (p0.y & 0xFFFF)) * 32]);
        float2 v1 = __half22float2(hb[(((size_t)(p1.y >> 16)) * NN + (p1.y & 0xFFFF)) * 32]);
        float2 v2 = __half22float2(hb[(((size_t)(p2.y >> 16)) * NN + (p2.y & 0xFFFF)) * 32]);
        float2 v3 = __half22float2(hb[(((size_t)(p3.y >> 16)) * NN + (p3.y & 0xFFFF)) * 32]);
        float i0 = __uint_as_float(p0.x);
        float i1 = __uint_as_float(p1.x);
        float i2 = __uint_as_float(p2.x);
        float i3 = __uint_as_float(p3.x);
        a0.x += v0.x * i0; a0.y += v0.y * i0;
        a1.x += v1.x * i1; a1.y += v1.y * i1;
        a2.x += v2.x * i2; a2.y += v2.y * i2;
        a3.x += v3.x * i3; a3.y += v3.y * i3;
    }
    for (; e < end; e++) {
        uint2 p = g_eperm2[e];
        float iv = __uint_as_float(p.x);
        float2 v = __half22float2(hb[(((size_t)(p.y >> 16)) * NN + (p.y & 0xFFFF)) * 32]);
        a0.x += v.x * iv; a0.y += v.y * iv;
    }
    a0.x += a1.x + a2.x + a3.x;
    a0.y += a1.y + a2.y + a3.y;

    if (layer == 0) {
        *(float2*)agg = a0;                            // relu applied by layer-2 gemm load
    } else {
        float rx = fmaxf(a0.x, 0.f);
        float ry = fmaxf(a0.y, 0.f);
        float* p = g_pool + batch[w] * 64 + lane * 2;
        asm volatile("red.global.add.v2.f32 [%0], {%1,%2};"
                     :: "l"(p), "f"(rx), "f"(ry) : "memory");
    }
}

// ---------------- classifier; zeros g_pool after reading (self-clean) ----------
__global__ void __launch_bounds__(256) classify(const int* __restrict__ batch,
                                                const float* __restrict__ w,
                                                const float* __restrict__ b,
                                                float* __restrict__ out) {
    int t = blockIdx.x * blockDim.x + threadIdx.x;
    int g = t / CC, c = t % CC;
    int lo = 0, hi = NN;
    while (lo < hi) { int m = (lo + hi) >> 1; if (batch[m] < g) lo = m + 1; else hi = m; }
    int lo2 = lo, hi2 = NN;
    while (lo2 < hi2) { int m = (lo2 + hi2) >> 1; if (batch[m] < g + 1) lo2 = m + 1; else hi2 = m; }
    float inv = 1.f / fmaxf((float)(lo2 - lo), 1.f);
    float acc = b[c];
#pragma unroll
    for (int k = 0; k < 64; k++)
        acc += g_pool[g * 64 + k] * inv * w[k * CC + c];
    out[t] = acc;

    __syncthreads();
    float* pz = g_pool + blockIdx.x * 64 * 64;
    for (int i = threadIdx.x; i < 64 * 64; i += 256) pz[i] = 0.f;
}

// ---------------- launch ----------------
extern "C" void kernel_launch(void* const* d_in, const int* in_sizes, int n_in,
                              void* d_out, int out_size) {
    const float* x      = (const float*)d_in[0];
    const int*   ei     = (const int*)d_in[1];
    const int*   et     = (const int*)d_in[2];
    const int*   batch  = (const int*)d_in[3];
    const float* basis1 = (const float*)d_in[4];
    const float* comp1  = (const float*)d_in[5];
    const float* root1  = (const float*)d_in[6];
    const float* bias1  = (const float*)d_in[7];
    const float* basis2 = (const float*)d_in[8];
    const float* comp2  = (const float*)d_in[9];
    const float* root2  = (const float*)d_in[10];
    const float* bias2  = (const float*)d_in[11];
    const float* clw    = (const float*)d_in[12];
    const float* clb    = (const float*)d_in[13];
    float* out = (float*)d_out;

    const int* src = ei;
    const int* dstp = ei + EE;

    static int inited = 0;
    static cudaStream_t s1;
    static cudaEvent_t ev0, ev1;
    if (!inited) {
        cudaFuncSetAttribute(gemm_tc, cudaFuncAttributeMaxDynamicSharedMemorySize,
                             GEMM_SMEM);
        cudaStreamCreateWithFlags(&s1, cudaStreamNonBlocking);
        cudaEventCreateWithFlags(&ev0, cudaEventDisableTiming);
        cudaEventCreateWithFlags(&ev1, cudaEventDisableTiming);
        inited = 1;
    }

    int gblocks = (NN + 127) / 128;   // 391

    // ---- init (weights) ----
    init_w<<<160, 256>>>(basis1, comp1, root1, basis2, comp2, root2);

    // ---- fork: gemm1 on side stream; CSR build on main stream ----
    cudaEventRecord(ev0, 0);
    cudaStreamWaitEvent(s1, ev0, 0);
    gemm_tc<<<gblocks, 256, GEMM_SMEM, s1>>>(x, bias1, 0);
    cudaEventRecord(ev1, s1);

    count_edges<<<EE / 256, 256>>>(dstp, et);
    scan_phase1<<<NBLK, 256>>>();
    scan_phase2<<<NBLK, 256>>>();
    build_perm<<<EE / 256, 256>>>(src, dstp, et);

    // ---- join, then layer-1 aggregation ----
    cudaStreamWaitEvent(0, ev1, 0);
    agg_edges<<<(NN * 32 + 255) / 256, 256>>>(batch, 0);

    // ---- layer 2 ----
    gemm_tc<<<gblocks, 256, GEMM_SMEM>>>(x, bias2, 1);
    agg_edges<<<(NN * 32 + 255) / 256, 256>>>(batch, 1);   // fused relu + pool

    // ---- classifier ----
    classify<<<(GG * CC) / 256, 256>>>(batch, clw, clb, out);
}